// round 11
// baseline (speedup 1.0000x reference)
#include <cuda_runtime.h>
#include <math.h>
#include <stdint.h>

#define NN      1536
#define FIN     1433
#define NH      64
#define HEADS   8
#define HF      8
#define NC      7
#define MAXDEG  48
#define NEG_SLOPE 0.2f

#define TILES   24          // 1536 / 64 rows
#define KSPLIT  32
#define KCH     46          // K per split (32*46=1472 >= 1433, zero-padded)
#define KP      23          // k-pairs per split (odd -> conflict-free strides)

// ---------------- scratch ---------------------------------------------------
__device__ float g_p[KSPLIT][NN * NH];   // gemm K-split partials
__device__ float g_g1[NN * NH];          // reduced x @ W1
__device__ float g_g2[NN * NC];          // elu(attn1) @ W2
__device__ int   g_nbr[NN * MAXDEG];
__device__ int   g_cnt[NN];
__device__ int   g_tick[TILES];          // reduction tickets (self-resetting)

// ---------------- K1: fused GEMM1 (768 blocks) + CSR (192 blocks) -----------
// gemm block (256 thr): tile = bx>>5 (64 rows x 64 cols), ks = bx&31 (K=46)
//   thread: rg = tid>>3 -> rows rg*2, rg*2+1 ; cg = tid&7 -> cols cg*8..+7
//   k-paired f32x2: acc.lo = even-k partial, acc.hi = odd-k partial.
__global__ __launch_bounds__(256) void k_main(const float* __restrict__ x,
                                              const float* __restrict__ W1,
                                              const unsigned char* __restrict__ adjb) {
    if (blockIdx.x < TILES * KSPLIT) {
        __shared__ unsigned long long xs[64 * KP];        // [row][pair]
        __shared__ unsigned long long ws[8 * KP * 8];     // [j][pair][cgrp]

        int tile = blockIdx.x >> 5;
        int ks   = blockIdx.x & 31;
        int row0 = tile * 64;
        int kbeg = ks * KCH;
        int kend = kbeg + KCH; if (kend > FIN) kend = FIN;
        int klen = kend - kbeg;
        int tid  = threadIdx.x;
        int rg   = tid >> 3;
        int cg   = tid & 7;

        unsigned int* xsw = (unsigned int*)xs;
        for (int l = tid; l < 64 * KCH; l += 256) {
            int row = l / KCH, k = l - row * KCH;
            float v = (k < klen) ? x[(size_t)(row0 + row) * FIN + kbeg + k] : 0.f;
            xsw[row * KCH + k] = __float_as_uint(v);
        }
        unsigned int* wsw = (unsigned int*)ws;
        for (int l = tid; l < KCH * 64; l += 256) {
            int k = l >> 6, c = l & 63;
            float v = (k < klen) ? W1[(size_t)(kbeg + k) * NH + c] : 0.f;
            wsw[(c & 7) * (KP * 16) + (k >> 1) * 16 + ((c >> 3) << 1) + (k & 1)]
                = __float_as_uint(v);
        }
        __syncthreads();

        unsigned long long acc[2][8];
        #pragma unroll
        for (int i = 0; i < 2; i++)
            #pragma unroll
            for (int j = 0; j < 8; j++) acc[i][j] = 0ull;

        for (int p = 0; p < KP; p++) {
            unsigned long long x0 = xs[(rg * 2 + 0) * KP + p];
            unsigned long long x1 = xs[(rg * 2 + 1) * KP + p];
            #pragma unroll
            for (int j = 0; j < 8; j++) {
                unsigned long long wv = ws[j * (KP * 8) + p * 8 + cg];
                asm("fma.rn.f32x2 %0, %1, %2, %0;" : "+l"(acc[0][j]) : "l"(x0), "l"(wv));
                asm("fma.rn.f32x2 %0, %1, %2, %0;" : "+l"(acc[1][j]) : "l"(x1), "l"(wv));
            }
        }

        #pragma unroll
        for (int i = 0; i < 2; i++) {
            float* dst = g_p[ks] + (size_t)(row0 + rg * 2 + i) * NH + cg * 8;
            #pragma unroll
            for (int j = 0; j < 8; j += 2) {
                unsigned l0, h0, l1, h1;
                asm("mov.b64 {%0,%1}, %2;" : "=r"(l0), "=r"(h0) : "l"(acc[i][j]));
                asm("mov.b64 {%0,%1}, %2;" : "=r"(l1), "=r"(h1) : "l"(acc[i][j + 1]));
                float2 v = make_float2(__uint_as_float(l0) + __uint_as_float(h0),
                                       __uint_as_float(l1) + __uint_as_float(h1));
                *(float2*)(dst + j) = v;
            }
        }

        // last-arriving split block reduces the 32 partials for this tile
        __shared__ int s_last;
        __threadfence();
        __syncthreads();
        if (tid == 0) {
            int old = atomicAdd(&g_tick[tile], 1);
            s_last = (old == KSPLIT - 1);
        }
        __syncthreads();
        if (s_last) {
            for (int l = tid; l < 64 * 16; l += 256) {    // float4 units
                float4 s = make_float4(0.f, 0.f, 0.f, 0.f);
                #pragma unroll
                for (int q = 0; q < KSPLIT; q++) {
                    float4 v = *(const float4*)(g_p[q] + (size_t)row0 * NH + l * 4);
                    s.x += v.x; s.y += v.y; s.z += v.z; s.w += v.w;
                }
                *(float4*)(g_g1 + (size_t)row0 * NH + l * 4) = s;
            }
            if (tid == 0) g_tick[tile] = 0;   // reset for next graph replay
        }
    } else {
        // ---------------- CSR path (8 rows/block, warp per row) ----------------
        int cb   = blockIdx.x - TILES * KSPLIT;
        int row  = cb * 8 + (threadIdx.x >> 5);
        int lane = threadIdx.x & 31;
        // dtype probe: bytes i*(NN+1), i=1..3 are diagonal self-loops for u8
        // (nonzero) but land on bytes 1..3 of 4-byte widened bool (zero).
        bool isu8 = adjb[1 * (NN + 1)] && adjb[2 * (NN + 1)] && adjb[3 * (NN + 1)];
        unsigned m[48];
        if (isu8) {
            const unsigned char* rp = adjb + (size_t)row * NN;
            #pragma unroll
            for (int q = 0; q < 48; q++)
                m[q] = __ballot_sync(0xffffffffu, rp[q * 32 + lane] != 0);
        } else {
            const unsigned int* rp = (const unsigned int*)adjb + (size_t)row * NN;
            #pragma unroll
            for (int q = 0; q < 48; q++)
                m[q] = __ballot_sync(0xffffffffu, rp[q * 32 + lane] != 0u);
        }
        int base = 0;
        #pragma unroll
        for (int q = 0; q < 48; q++) {
            unsigned b = m[q];
            if (b & (1u << lane)) {
                int pos = base + __popc(b & ((1u << lane) - 1u));
                if (pos < MAXDEG) g_nbr[row * MAXDEG + pos] = q * 32 + lane;
            }
            base += __popc(b);
        }
        if (lane == 0) g_cnt[row] = base < MAXDEG ? base : MAXDEG;
    }
}

// ---------------- K2: attn layer1 + ELU + GEMM2 fused ------------------------
__global__ __launch_bounds__(128) void k_attn1(const float* __restrict__ a1v,
                                               const float* __restrict__ W2) {
    __shared__ int   nb[2][MAXDEG];
    __shared__ float rows[2][MAXDEG][65];
    __shared__ float es[2][MAXDEG][HEADS];
    __shared__ float gis[2][64];
    __shared__ float ssum[2][HEADS];
    __shared__ float h1s[2][64];
    __shared__ float a1s[HF];
    __shared__ float w2s[NH * NC];

    int node = threadIdx.x >> 6;
    int t    = threadIdx.x & 63;
    int i    = blockIdx.x * 2 + node;
    int cnt  = g_cnt[i];

    if (threadIdx.x < HF) a1s[threadIdx.x] = a1v[threadIdx.x];
    for (int l = threadIdx.x; l < NH * NC; l += 128) w2s[l] = W2[l];
    if (t < cnt) nb[node][t] = g_nbr[i * MAXDEG + t];
    gis[node][t] = g_g1[(size_t)i * NH + t];
    __syncthreads();

    #pragma unroll 4
    for (int j = 0; j < cnt; j++)
        rows[node][j][t] = g_g1[(size_t)nb[node][j] * NH + t];
    __syncthreads();

    // scores e[j][h] = sum_f a1[f] * lrelu(gi[h,f] + gj[h,f])
    {
        int jl = t >> 3, h = t & 7;
        for (int j0 = 0; j0 < cnt; j0 += 8) {
            int j = j0 + jl;
            if (j < cnt) {
                float e = 0.f;
                #pragma unroll
                for (int f = 0; f < 8; f++) {
                    float s = gis[node][h * 8 + f] + rows[node][j][h * 8 + f];
                    s = (s > 0.f) ? s : NEG_SLOPE * s;
                    e += a1s[f] * s;
                }
                es[node][j][h] = e;
            }
        }
    }
    __syncthreads();

    if (t < HEADS) {
        int h = t;
        float m = -INFINITY;
        for (int j = 0; j < cnt; j++) m = fmaxf(m, es[node][j][h]);
        float s = 0.f;
        for (int j = 0; j < cnt; j++) {
            float w = __expf(es[node][j][h] - m);
            es[node][j][h] = w;
            s += w;
        }
        ssum[node][h] = s;
    }
    __syncthreads();

    {
        int h = t >> 3;
        float acc = 0.f;
        for (int j = 0; j < cnt; j++)
            acc += es[node][j][h] * rows[node][j][t];
        acc /= ssum[node][h];
        h1s[node][t] = (acc > 0.f) ? acc : (__expf(acc) - 1.f);
    }
    __syncthreads();

    if (t < NC) {
        float acc = 0.f;
        #pragma unroll
        for (int k = 0; k < NH; k++) acc += h1s[node][k] * w2s[k * NC + t];
        g_g2[(size_t)i * NC + t] = acc;
    }
}

// ---------------- K3: attn layer 2 (1 head, 7 feats) -------------------------
__global__ void k_attn2(const float* __restrict__ a2v, float* __restrict__ out) {
    int warp = threadIdx.x >> 5;
    int lane = threadIdx.x & 31;
    int i = blockIdx.x * 4 + warp;
    if (i >= NN) return;

    int cnt = g_cnt[i];
    float a2r[NC], g2i[NC];
    #pragma unroll
    for (int c = 0; c < NC; c++) {
        a2r[c] = a2v[c];
        g2i[c] = g_g2[(size_t)i * NC + c];
    }

    const int QMAX = (MAXDEG + 31) / 32;   // 2
    int   njv[QMAX];
    float ev[QMAX];
    int nq = 0;
    float m = -INFINITY;
    for (int jj = lane; jj < cnt; jj += 32) {
        int nj = g_nbr[i * MAXDEG + jj];
        njv[nq] = nj;
        float e = 0.f;
        #pragma unroll
        for (int c = 0; c < NC; c++) {
            float s = g2i[c] + g_g2[(size_t)nj * NC + c];
            s = (s > 0.f) ? s : NEG_SLOPE * s;
            e += a2r[c] * s;
        }
        ev[nq++] = e;
        m = fmaxf(m, e);
    }
    #pragma unroll
    for (int o = 16; o > 0; o >>= 1) m = fmaxf(m, __shfl_xor_sync(0xffffffffu, m, o));

    float sum = 0.f;
    float acc[NC];
    #pragma unroll
    for (int c = 0; c < NC; c++) acc[c] = 0.f;
    for (int q = 0; q < nq; q++) {
        float w = __expf(ev[q] - m);
        sum += w;
        #pragma unroll
        for (int c = 0; c < NC; c++) acc[c] += w * g_g2[(size_t)njv[q] * NC + c];
    }
    #pragma unroll
    for (int o = 16; o > 0; o >>= 1) sum += __shfl_xor_sync(0xffffffffu, sum, o);
    float inv = 1.f / sum;

    #pragma unroll
    for (int c = 0; c < NC; c++) {
        float v = acc[c];
        #pragma unroll
        for (int o = 16; o > 0; o >>= 1) v += __shfl_xor_sync(0xffffffffu, v, o);
        if (lane == 0) out[(size_t)i * NC + c] = v * inv;
    }
}

// ---------------------------------------------------------------------------
extern "C" void kernel_launch(void* const* d_in, const int* in_sizes, int n_in,
                              void* d_out, int out_size) {
    const float*         x   = (const float*)d_in[0];
    const unsigned char* adj = (const unsigned char*)d_in[1];
    const float*         W1  = (const float*)d_in[2];
    const float*         a1  = (const float*)d_in[3];
    const float*         W2  = (const float*)d_in[4];
    const float*         a2  = (const float*)d_in[5];
    float*               out = (float*)d_out;

    k_main <<<TILES * KSPLIT + NN / 8, 256>>>(x, W1, adj);
    k_attn1<<<NN / 2, 128>>>(a1, W2);
    k_attn2<<<(NN + 3) / 4, 128>>>(a2, out);
}

// round 14
// speedup vs baseline: 1.1071x; 1.1071x over previous
#include <cuda_runtime.h>
#include <math.h>
#include <stdint.h>

#define NN      1536
#define FIN     1433
#define NH      64
#define HEADS   8
#define HF      8
#define NC      7
#define MAXDEG  48
#define NEG_SLOPE 0.2f

#define TILES   24          // 1536 / 64 rows
#define KSPLIT  16
#define KCH     90          // K per split (last covers 83, zero-padded)
#define KP      45          // k-pairs per split (odd -> conflict-free strides)

// ---------------- scratch ---------------------------------------------------
__device__ float g_p[KSPLIT][NN * NH];   // gemm K-split partials
__device__ float g_g1[NN * NH];          // reduced x @ W1
__device__ float g_g2[NN * NC];          // elu(attn1) @ W2
__device__ int   g_nbr[NN * MAXDEG];
__device__ int   g_cnt[NN];
__device__ int   g_tick[TILES];          // reduction tickets (self-resetting)

// ---------------- K1: fused GEMM1 (384 blocks) + CSR (192 blocks) -----------
// ONE wave: 576 blocks of 256 thr, regs<=64 -> 4 blocks/SM -> 592 slots.
// gemm block: tile = bx>>4 (64x64), ks = bx&15 (k-range of 90).
//   thread: rg = tid>>3 -> rows rg*2, rg*2+1 ; cg = tid&7 -> cols cg*8..+7
//   k-paired f32x2: acc.lo = even-k partial, acc.hi = odd-k partial.
__global__ __launch_bounds__(256) void k_main(const float* __restrict__ x,
                                              const float* __restrict__ W1,
                                              const unsigned char* __restrict__ adjb) {
    if (blockIdx.x < TILES * KSPLIT) {
        __shared__ unsigned long long xs[64 * KP];        // [row][pair]
        __shared__ unsigned long long ws[8 * KP * 8];     // [j][pair][cgrp]

        int tile = blockIdx.x >> 4;
        int ks   = blockIdx.x & 15;
        int row0 = tile * 64;
        int kbeg = ks * KCH;
        int kend = kbeg + KCH; if (kend > FIN) kend = FIN;
        int klen = kend - kbeg;
        int tid  = threadIdx.x;
        int rg   = tid >> 3;
        int cg   = tid & 7;
        int wid  = tid >> 5;
        int lane = tid & 31;

        // x fill: warp per row group (no integer division), coalesced
        unsigned int* xsw = (unsigned int*)xs;
        for (int r = wid; r < 64; r += 8) {
            const float* src = x + (size_t)(row0 + r) * FIN + kbeg;
            for (int k = lane; k < KCH; k += 32) {
                float v = (k < klen) ? src[k] : 0.f;
                xsw[r * KCH + k] = __float_as_uint(v);
            }
        }
        // W fill transposed to [j][pair][cgrp] word layout (shift-only math)
        unsigned int* wsw = (unsigned int*)ws;
        for (int l = tid; l < KCH * 64; l += 256) {
            int k = l >> 6, c = l & 63;
            float v = (k < klen) ? W1[(size_t)(kbeg + k) * NH + c] : 0.f;
            wsw[(c & 7) * (KP * 16) + (k >> 1) * 16 + ((c >> 3) << 1) + (k & 1)]
                = __float_as_uint(v);
        }
        __syncthreads();

        unsigned long long acc[2][8];
        #pragma unroll
        for (int i = 0; i < 2; i++)
            #pragma unroll
            for (int j = 0; j < 8; j++) acc[i][j] = 0ull;

        for (int p = 0; p < KP; p++) {
            unsigned long long x0 = xs[(rg * 2 + 0) * KP + p];
            unsigned long long x1 = xs[(rg * 2 + 1) * KP + p];
            #pragma unroll
            for (int j = 0; j < 8; j++) {
                unsigned long long wv = ws[j * (KP * 8) + p * 8 + cg];
                asm("fma.rn.f32x2 %0, %1, %2, %0;" : "+l"(acc[0][j]) : "l"(x0), "l"(wv));
                asm("fma.rn.f32x2 %0, %1, %2, %0;" : "+l"(acc[1][j]) : "l"(x1), "l"(wv));
            }
        }

        #pragma unroll
        for (int i = 0; i < 2; i++) {
            float* dst = g_p[ks] + (size_t)(row0 + rg * 2 + i) * NH + cg * 8;
            #pragma unroll
            for (int j = 0; j < 8; j += 2) {
                unsigned l0, h0, l1, h1;
                asm("mov.b64 {%0,%1}, %2;" : "=r"(l0), "=r"(h0) : "l"(acc[i][j]));
                asm("mov.b64 {%0,%1}, %2;" : "=r"(l1), "=r"(h1) : "l"(acc[i][j + 1]));
                float2 v = make_float2(__uint_as_float(l0) + __uint_as_float(h0),
                                       __uint_as_float(l1) + __uint_as_float(h1));
                *(float2*)(dst + j) = v;
            }
        }

        // last-arriving split block reduces the 16 partials for this tile
        __shared__ int s_last;
        __threadfence();
        __syncthreads();
        if (tid == 0) {
            int old = atomicAdd(&g_tick[tile], 1);
            s_last = (old == KSPLIT - 1);
        }
        __syncthreads();
        if (s_last) {
            for (int l = tid; l < 64 * 16; l += 256) {    // float4 units
                float4 s = make_float4(0.f, 0.f, 0.f, 0.f);
                #pragma unroll
                for (int q = 0; q < KSPLIT; q++) {
                    float4 v = *(const float4*)(g_p[q] + (size_t)row0 * NH + l * 4);
                    s.x += v.x; s.y += v.y; s.z += v.z; s.w += v.w;
                }
                *(float4*)(g_g1 + (size_t)row0 * NH + l * 4) = s;
            }
            if (tid == 0) g_tick[tile] = 0;   // reset for next graph replay
        }
    } else {
        // ---------------- CSR path (8 rows/block, warp per row) ----------------
        int cb   = blockIdx.x - TILES * KSPLIT;
        int row  = cb * 8 + (threadIdx.x >> 5);
        int lane = threadIdx.x & 31;
        // dtype probe: bytes i*(NN+1), i=1..3 are diagonal self-loops for u8
        // (nonzero) but land on bytes 1..3 of 4-byte widened bool (zero).
        bool isu8 = adjb[1 * (NN + 1)] && adjb[2 * (NN + 1)] && adjb[3 * (NN + 1)];
        unsigned m[48];
        if (isu8) {
            const unsigned char* rp = adjb + (size_t)row * NN;
            #pragma unroll
            for (int q = 0; q < 48; q++)
                m[q] = __ballot_sync(0xffffffffu, rp[q * 32 + lane] != 0);
        } else {
            const unsigned int* rp = (const unsigned int*)adjb + (size_t)row * NN;
            #pragma unroll
            for (int q = 0; q < 48; q++)
                m[q] = __ballot_sync(0xffffffffu, rp[q * 32 + lane] != 0u);
        }
        int base = 0;
        #pragma unroll
        for (int q = 0; q < 48; q++) {
            unsigned b = m[q];
            if (b & (1u << lane)) {
                int pos = base + __popc(b & ((1u << lane) - 1u));
                if (pos < MAXDEG) g_nbr[row * MAXDEG + pos] = q * 32 + lane;
            }
            base += __popc(b);
        }
        if (lane == 0) g_cnt[row] = base < MAXDEG ? base : MAXDEG;
    }
}

// ---------------- K2: attn layer1 + ELU + GEMM2 fused ------------------------
__global__ __launch_bounds__(128) void k_attn1(const float* __restrict__ a1v,
                                               const float* __restrict__ W2) {
    __shared__ int   nb[2][MAXDEG];
    __shared__ float rows[2][MAXDEG][65];
    __shared__ float es[2][MAXDEG][HEADS];
    __shared__ float gis[2][64];
    __shared__ float ssum[2][HEADS];
    __shared__ float h1s[2][64];
    __shared__ float a1s[HF];
    __shared__ float w2s[NH * NC];

    int node = threadIdx.x >> 6;
    int t    = threadIdx.x & 63;
    int i    = blockIdx.x * 2 + node;
    int cnt  = g_cnt[i];

    if (threadIdx.x < HF) a1s[threadIdx.x] = a1v[threadIdx.x];
    for (int l = threadIdx.x; l < NH * NC; l += 128) w2s[l] = W2[l];
    if (t < cnt) nb[node][t] = g_nbr[i * MAXDEG + t];
    gis[node][t] = g_g1[(size_t)i * NH + t];
    __syncthreads();

    #pragma unroll 4
    for (int j = 0; j < cnt; j++)
        rows[node][j][t] = g_g1[(size_t)nb[node][j] * NH + t];
    __syncthreads();

    // scores e[j][h] = sum_f a1[f] * lrelu(gi[h,f] + gj[h,f])
    {
        int jl = t >> 3, h = t & 7;
        for (int j0 = 0; j0 < cnt; j0 += 8) {
            int j = j0 + jl;
            if (j < cnt) {
                float e = 0.f;
                #pragma unroll
                for (int f = 0; f < 8; f++) {
                    float s = gis[node][h * 8 + f] + rows[node][j][h * 8 + f];
                    s = (s > 0.f) ? s : NEG_SLOPE * s;
                    e += a1s[f] * s;
                }
                es[node][j][h] = e;
            }
        }
    }
    __syncthreads();

    if (t < HEADS) {
        int h = t;
        float m = -INFINITY;
        for (int j = 0; j < cnt; j++) m = fmaxf(m, es[node][j][h]);
        float s = 0.f;
        for (int j = 0; j < cnt; j++) {
            float w = __expf(es[node][j][h] - m);
            es[node][j][h] = w;
            s += w;
        }
        ssum[node][h] = s;
    }
    __syncthreads();

    {
        int h = t >> 3;
        float acc = 0.f;
        for (int j = 0; j < cnt; j++)
            acc += es[node][j][h] * rows[node][j][t];
        acc /= ssum[node][h];
        h1s[node][t] = (acc > 0.f) ? acc : (__expf(acc) - 1.f);
    }
    __syncthreads();

    if (t < NC) {
        float acc = 0.f;
        #pragma unroll
        for (int k = 0; k < NH; k++) acc += h1s[node][k] * w2s[k * NC + t];
        g_g2[(size_t)i * NC + t] = acc;
    }
}

// ---------------- K3: attn layer 2 (1 head, 7 feats) -------------------------
__global__ void k_attn2(const float* __restrict__ a2v, float* __restrict__ out) {
    int warp = threadIdx.x >> 5;
    int lane = threadIdx.x & 31;
    int i = blockIdx.x * 4 + warp;
    if (i >= NN) return;

    int cnt = g_cnt[i];
    float a2r[NC], g2i[NC];
    #pragma unroll
    for (int c = 0; c < NC; c++) {
        a2r[c] = a2v[c];
        g2i[c] = g_g2[(size_t)i * NC + c];
    }

    const int QMAX = (MAXDEG + 31) / 32;   // 2
    int   njv[QMAX];
    float ev[QMAX];
    int nq = 0;
    float m = -INFINITY;
    for (int jj = lane; jj < cnt; jj += 32) {
        int nj = g_nbr[i * MAXDEG + jj];
        njv[nq] = nj;
        float e = 0.f;
        #pragma unroll
        for (int c = 0; c < NC; c++) {
            float s = g2i[c] + g_g2[(size_t)nj * NC + c];
            s = (s > 0.f) ? s : NEG_SLOPE * s;
            e += a2r[c] * s;
        }
        ev[nq++] = e;
        m = fmaxf(m, e);
    }
    #pragma unroll
    for (int o = 16; o > 0; o >>= 1) m = fmaxf(m, __shfl_xor_sync(0xffffffffu, m, o));

    float sum = 0.f;
    float acc[NC];
    #pragma unroll
    for (int c = 0; c < NC; c++) acc[c] = 0.f;
    for (int q = 0; q < nq; q++) {
        float w = __expf(ev[q] - m);
        sum += w;
        #pragma unroll
        for (int c = 0; c < NC; c++) acc[c] += w * g_g2[(size_t)njv[q] * NC + c];
    }
    #pragma unroll
    for (int o = 16; o > 0; o >>= 1) sum += __shfl_xor_sync(0xffffffffu, sum, o);
    float inv = 1.f / sum;

    #pragma unroll
    for (int c = 0; c < NC; c++) {
        float v = acc[c];
        #pragma unroll
        for (int o = 16; o > 0; o >>= 1) v += __shfl_xor_sync(0xffffffffu, v, o);
        if (lane == 0) out[(size_t)i * NC + c] = v * inv;
    }
}

// ---------------------------------------------------------------------------
extern "C" void kernel_launch(void* const* d_in, const int* in_sizes, int n_in,
                              void* d_out, int out_size) {
    const float*         x   = (const float*)d_in[0];
    const unsigned char* adj = (const unsigned char*)d_in[1];
    const float*         W1  = (const float*)d_in[2];
    const float*         a1  = (const float*)d_in[3];
    const float*         W2  = (const float*)d_in[4];
    const float*         a2  = (const float*)d_in[5];
    float*               out = (float*)d_out;

    k_main <<<TILES * KSPLIT + NN / 8, 256>>>(x, W1, adj);
    k_attn1<<<NN / 2, 128>>>(a1, W2);
    k_attn2<<<(NN + 3) / 4, 128>>>(a2, out);
}

// round 15
// speedup vs baseline: 1.1419x; 1.0314x over previous
#include <cuda_runtime.h>
#include <math.h>
#include <stdint.h>

#define NN      1536
#define FIN     1433
#define NH      64
#define HEADS   8
#define HF      8
#define NC      7
#define MAXDEG  48
#define NEG_SLOPE 0.2f

#define TILES   24          // 1536 / 64 rows
#define KSPLIT  16
#define KCH     90          // K per split (last covers 83, zero-padded)
#define KP      45          // k-pairs per split (odd -> conflict-free strides)

// ---------------- scratch ---------------------------------------------------
__device__ float g_p[KSPLIT][NN * NH];   // gemm K-split partials
__device__ float g_g1[NN * NH];          // reduced x @ W1
__device__ float g_g2[NN * NC];          // elu(attn1) @ W2
__device__ int   g_nbr[NN * MAXDEG];
__device__ int   g_cnt[NN];
__device__ int   g_tick[TILES];          // reduction tickets (self-resetting)
__device__ int   g_flag[NN];             // attn1->attn2 ready flags (reset in k_main)

// ---------------- K1: fused GEMM1 (384 blocks) + CSR (192 blocks) -----------
// ONE wave: 576 blocks of 256 thr, regs<=64 -> 4 blocks/SM -> 592 slots.
__global__ __launch_bounds__(256) void k_main(const float* __restrict__ x,
                                              const float* __restrict__ W1,
                                              const unsigned char* __restrict__ adjb) {
    if (blockIdx.x < TILES * KSPLIT) {
        __shared__ unsigned long long xs[64 * KP];        // [row][pair]
        __shared__ unsigned long long ws[8 * KP * 8];     // [j][pair][cgrp]

        int tile = blockIdx.x >> 4;
        int ks   = blockIdx.x & 15;
        int row0 = tile * 64;
        int kbeg = ks * KCH;
        int kend = kbeg + KCH; if (kend > FIN) kend = FIN;
        int klen = kend - kbeg;
        int tid  = threadIdx.x;
        int rg   = tid >> 3;
        int cg   = tid & 7;
        int wid  = tid >> 5;
        int lane = tid & 31;

        // x fill: warp per row (no integer division), coalesced
        unsigned int* xsw = (unsigned int*)xs;
        for (int r = wid; r < 64; r += 8) {
            const float* src = x + (size_t)(row0 + r) * FIN + kbeg;
            for (int k = lane; k < KCH; k += 32) {
                float v = (k < klen) ? src[k] : 0.f;
                xsw[r * KCH + k] = __float_as_uint(v);
            }
        }
        // W fill transposed to [j][pair][cgrp] word layout
        unsigned int* wsw = (unsigned int*)ws;
        for (int l = tid; l < KCH * 64; l += 256) {
            int k = l >> 6, c = l & 63;
            float v = (k < klen) ? W1[(size_t)(kbeg + k) * NH + c] : 0.f;
            wsw[(c & 7) * (KP * 16) + (k >> 1) * 16 + ((c >> 3) << 1) + (k & 1)]
                = __float_as_uint(v);
        }
        __syncthreads();

        unsigned long long acc[2][8];
        #pragma unroll
        for (int i = 0; i < 2; i++)
            #pragma unroll
            for (int j = 0; j < 8; j++) acc[i][j] = 0ull;

        for (int p = 0; p < KP; p++) {
            unsigned long long x0 = xs[(rg * 2 + 0) * KP + p];
            unsigned long long x1 = xs[(rg * 2 + 1) * KP + p];
            #pragma unroll
            for (int j = 0; j < 8; j++) {
                unsigned long long wv = ws[j * (KP * 8) + p * 8 + cg];
                asm("fma.rn.f32x2 %0, %1, %2, %0;" : "+l"(acc[0][j]) : "l"(x0), "l"(wv));
                asm("fma.rn.f32x2 %0, %1, %2, %0;" : "+l"(acc[1][j]) : "l"(x1), "l"(wv));
            }
        }

        #pragma unroll
        for (int i = 0; i < 2; i++) {
            float* dst = g_p[ks] + (size_t)(row0 + rg * 2 + i) * NH + cg * 8;
            #pragma unroll
            for (int j = 0; j < 8; j += 2) {
                unsigned l0, h0, l1, h1;
                asm("mov.b64 {%0,%1}, %2;" : "=r"(l0), "=r"(h0) : "l"(acc[i][j]));
                asm("mov.b64 {%0,%1}, %2;" : "=r"(l1), "=r"(h1) : "l"(acc[i][j + 1]));
                float2 v = make_float2(__uint_as_float(l0) + __uint_as_float(h0),
                                       __uint_as_float(l1) + __uint_as_float(h1));
                *(float2*)(dst + j) = v;
            }
        }

        // last-arriving split block reduces the 16 partials for this tile
        __shared__ int s_last;
        __threadfence();
        __syncthreads();
        if (tid == 0) {
            int old = atomicAdd(&g_tick[tile], 1);
            s_last = (old == KSPLIT - 1);
        }
        __syncthreads();
        if (s_last) {
            for (int l = tid; l < 64 * 16; l += 256) {    // float4 units
                float4 s = make_float4(0.f, 0.f, 0.f, 0.f);
                #pragma unroll
                for (int q = 0; q < KSPLIT; q++) {
                    float4 v = *(const float4*)(g_p[q] + (size_t)row0 * NH + l * 4);
                    s.x += v.x; s.y += v.y; s.z += v.z; s.w += v.w;
                }
                *(float4*)(g_g1 + (size_t)row0 * NH + l * 4) = s;
            }
            if (tid == 0) g_tick[tile] = 0;   // reset for next graph replay
        }
    } else {
        // ---------------- CSR path (8 rows/block, warp per row) ----------------
        int cb   = blockIdx.x - TILES * KSPLIT;
        int row  = cb * 8 + (threadIdx.x >> 5);
        int lane = threadIdx.x & 31;
        // dtype probe: bytes i*(NN+1), i=1..3 are diagonal self-loops for u8
        // (nonzero) but land on bytes 1..3 of 4-byte widened bool (zero).
        bool isu8 = adjb[1 * (NN + 1)] && adjb[2 * (NN + 1)] && adjb[3 * (NN + 1)];
        unsigned m[48];
        if (isu8) {
            const unsigned char* rp = adjb + (size_t)row * NN;
            #pragma unroll
            for (int q = 0; q < 48; q++)
                m[q] = __ballot_sync(0xffffffffu, rp[q * 32 + lane] != 0);
        } else {
            const unsigned int* rp = (const unsigned int*)adjb + (size_t)row * NN;
            #pragma unroll
            for (int q = 0; q < 48; q++)
                m[q] = __ballot_sync(0xffffffffu, rp[q * 32 + lane] != 0u);
        }
        int base = 0;
        #pragma unroll
        for (int q = 0; q < 48; q++) {
            unsigned b = m[q];
            if (b & (1u << lane)) {
                int pos = base + __popc(b & ((1u << lane) - 1u));
                if (pos < MAXDEG) g_nbr[row * MAXDEG + pos] = q * 32 + lane;
            }
            base += __popc(b);
        }
        if (lane == 0) {
            g_cnt[row]  = base < MAXDEG ? base : MAXDEG;
            g_flag[row] = 0;             // reset ready flag for this replay
        }
    }
}

// ---------------- K2: attn1 + ELU + GEMM2 + attn2 fused ---------------------
// 2 nodes per 128-thread block; flags gate the second layer. Deadlock-free:
// ~31KB smem -> 7 blocks/SM -> all 768 blocks co-resident.
__global__ __launch_bounds__(128) void k_attn(const float* __restrict__ a1v,
                                              const float* __restrict__ W2,
                                              const float* __restrict__ a2v,
                                              float* __restrict__ out) {
    __shared__ int   nb[2][MAXDEG];
    __shared__ float rows[2][MAXDEG][65];
    __shared__ float es[2][MAXDEG][HEADS];
    __shared__ float pm[2][HEADS][9];      // per-(head, jl) partials
    __shared__ float gis[2][64];
    __shared__ float mh[2][HEADS], ssum[2][HEADS];
    __shared__ float h1s[2][64];
    __shared__ float a1s[HF];
    __shared__ float a2s[NC];
    __shared__ float w2s[NH * NC];

    int node = threadIdx.x >> 6;
    int t    = threadIdx.x & 63;
    int i    = blockIdx.x * 2 + node;
    int cnt  = g_cnt[i];
    int jl   = t >> 3;
    int h    = t & 7;

    if (threadIdx.x < HF) a1s[threadIdx.x] = a1v[threadIdx.x];
    if (threadIdx.x >= 64 && threadIdx.x < 64 + NC) a2s[threadIdx.x - 64] = a2v[threadIdx.x - 64];
    for (int l = threadIdx.x; l < NH * NC; l += 128) w2s[l] = W2[l];
    if (t < cnt) nb[node][t] = g_nbr[i * MAXDEG + t];
    gis[node][t] = g_g1[(size_t)i * NH + t];
    __syncthreads();

    #pragma unroll 4
    for (int j = 0; j < cnt; j++)
        rows[node][j][t] = g_g1[(size_t)nb[node][j] * NH + t];
    __syncthreads();

    // scores e[j][h] = sum_f a1[f] * lrelu(gi[h,f] + gj[h,f]); (jl,h) parallel
    for (int j = jl; j < cnt; j += 8) {
        float e = 0.f;
        #pragma unroll
        for (int f = 0; f < 8; f++) {
            float s = gis[node][h * 8 + f] + rows[node][j][h * 8 + f];
            s = (s > 0.f) ? s : NEG_SLOPE * s;
            e += a1s[f] * s;
        }
        es[node][j][h] = e;
    }
    __syncthreads();

    // parallel softmax: partial max per (h, jl), 8-wide combine
    {
        float lm = -INFINITY;
        for (int j = jl; j < cnt; j += 8) lm = fmaxf(lm, es[node][j][h]);
        pm[node][h][jl] = lm;
    }
    __syncthreads();
    if (t < HEADS) {
        float m = pm[node][t][0];
        #pragma unroll
        for (int q = 1; q < 8; q++) m = fmaxf(m, pm[node][t][q]);
        mh[node][t] = m;
    }
    __syncthreads();
    {
        float m = mh[node][h];
        float ls = 0.f;
        for (int j = jl; j < cnt; j += 8) {
            float w = __expf(es[node][j][h] - m);
            es[node][j][h] = w;
            ls += w;
        }
        pm[node][h][jl] = ls;
    }
    __syncthreads();
    if (t < HEADS) {
        float s = 0.f;
        #pragma unroll
        for (int q = 0; q < 8; q++) s += pm[node][t][q];
        ssum[node][t] = s;
    }
    __syncthreads();

    // aggregate + ELU
    {
        int hh = t >> 3;
        float acc = 0.f;
        for (int j = 0; j < cnt; j++)
            acc += es[node][j][hh] * rows[node][j][t];
        acc /= ssum[node][hh];
        h1s[node][t] = (acc > 0.f) ? acc : (__expf(acc) - 1.f);
    }
    __syncthreads();

    // fused GEMM2 -> publish g_g2 row + ready flag
    if (t < NC) {
        float acc = 0.f;
        #pragma unroll
        for (int k = 0; k < NH; k++) acc += h1s[node][k] * w2s[k * NC + t];
        g_g2[(size_t)i * NC + t] = acc;
        __threadfence();
    }
    __syncthreads();
    if (t == 0) atomicExch(&g_flag[i], 1);

    // ---- phase 2: warp 0 of each half waits + computes layer 2 ----
    if (t < 32) {
        for (int jj = t; jj < cnt; jj += 32)
            while (((volatile int*)g_flag)[nb[node][jj]] == 0) { }
    }
    __syncthreads();
    __threadfence();

    if (t < 32) {
        int lane = t;
        float a2r[NC], g2i[NC];
        #pragma unroll
        for (int c = 0; c < NC; c++) {
            a2r[c] = a2s[c];
            g2i[c] = g_g2[(size_t)i * NC + c];
        }
        const int QMAX = (MAXDEG + 31) / 32;   // 2
        int   njv[QMAX];
        float ev[QMAX];
        int nq = 0;
        float m = -INFINITY;
        for (int jj = lane; jj < cnt; jj += 32) {
            int nj = nb[node][jj];
            njv[nq] = nj;
            float e = 0.f;
            #pragma unroll
            for (int c = 0; c < NC; c++) {
                float s = g2i[c] + g_g2[(size_t)nj * NC + c];
                s = (s > 0.f) ? s : NEG_SLOPE * s;
                e += a2r[c] * s;
            }
            ev[nq++] = e;
            m = fmaxf(m, e);
        }
        #pragma unroll
        for (int o = 16; o > 0; o >>= 1) m = fmaxf(m, __shfl_xor_sync(0xffffffffu, m, o));

        float sum = 0.f;
        float acc[NC];
        #pragma unroll
        for (int c = 0; c < NC; c++) acc[c] = 0.f;
        for (int q = 0; q < nq; q++) {
            float w = __expf(ev[q] - m);
            sum += w;
            #pragma unroll
            for (int c = 0; c < NC; c++) acc[c] += w * g_g2[(size_t)njv[q] * NC + c];
        }
        #pragma unroll
        for (int o = 16; o > 0; o >>= 1) sum += __shfl_xor_sync(0xffffffffu, sum, o);
        float inv = 1.f / sum;

        #pragma unroll
        for (int c = 0; c < NC; c++) {
            float v = acc[c];
            #pragma unroll
            for (int o = 16; o > 0; o >>= 1) v += __shfl_xor_sync(0xffffffffu, v, o);
            if (lane == 0) out[(size_t)i * NC + c] = v * inv;
        }
    }
}

// ---------------------------------------------------------------------------
extern "C" void kernel_launch(void* const* d_in, const int* in_sizes, int n_in,
                              void* d_out, int out_size) {
    const float*         x   = (const float*)d_in[0];
    const unsigned char* adj = (const unsigned char*)d_in[1];
    const float*         W1  = (const float*)d_in[2];
    const float*         a1  = (const float*)d_in[3];
    const float*         W2  = (const float*)d_in[4];
    const float*         a2  = (const float*)d_in[5];
    float*               out = (float*)d_out;

    k_main<<<TILES * KSPLIT + NN / 8, 256>>>(x, W1, adj);
    k_attn<<<NN / 2, 128>>>(a1, W2, a2, out);
}

// round 16
// speedup vs baseline: 1.1427x; 1.0008x over previous
#include <cuda_runtime.h>
#include <math.h>
#include <stdint.h>

#define NN      1536
#define FIN     1433
#define NH      64
#define HEADS   8
#define HF      8
#define NC      7
#define MAXDEG  48
#define NEG_SLOPE 0.2f

#define TILES   24          // 1536 / 64 rows
#define KSPLIT  16
#define KCH     90          // K per split (last covers 83, zero-padded)
#define KP      45          // k-pairs per split
#define NBLK    576         // 384 gemm + 192 csr; ONE co-resident wave (4/SM)

// ---------------- scratch ---------------------------------------------------
__device__ float g_p[KSPLIT][NN * NH];   // gemm K-split partials
__device__ float g_g1[NN * NH];          // reduced x @ W1
__device__ float g_g2[NN * NC];          // elu(attn1) @ W2
__device__ int   g_nbr[NN * MAXDEG];
__device__ int   g_cnt[NN];
__device__ int   g_tick[TILES];          // tile-reduction tickets (self-reset)
__device__ int   g_flag[NN];             // node-ready flags (reset in phase A)
__device__ int   g_done;                 // global barrier ticket (monotonic)

// shared-memory union: phase A gemm tile vs phase B attention workspace
union SmemU {
    struct {
        unsigned long long xs[64 * KP];     // [row][pair]
        unsigned long long ws[8 * KP * 8];  // [j][pair][cgrp]
    } g;                                     // 46080 B
    struct {
        int   nb[4][MAXDEG];
        float es[4][MAXDEG][HEADS];
        float gis[4][64];
        float pm[4][HEADS][9];
        float mh[4][HEADS];
        float ssum[4][HEADS];
        float h1s[4][64];
        float a1s[HF];
        float a2s[NC];
        float w2s[NH * NC];
    } a;                                     // ~12.3 KB
};

__global__ __launch_bounds__(256) void k_all(const float* __restrict__ x,
                                             const float* __restrict__ W1,
                                             const unsigned char* __restrict__ adjb,
                                             const float* __restrict__ a1v,
                                             const float* __restrict__ W2,
                                             const float* __restrict__ a2v,
                                             float* __restrict__ out) {
    __shared__ SmemU u;
    __shared__ int s_target;
    int tid = threadIdx.x;

    // ======================= PHASE A =======================
    if (blockIdx.x < TILES * KSPLIT) {
        // ---- GEMM1 K-split tile (64 rows x 64 cols x 90 K) ----
        int tile = blockIdx.x >> 4;
        int ks   = blockIdx.x & 15;
        int row0 = tile * 64;
        int kbeg = ks * KCH;
        int kend = kbeg + KCH; if (kend > FIN) kend = FIN;
        int klen = kend - kbeg;
        int rg   = tid >> 3;
        int cg   = tid & 7;
        int wid  = tid >> 5;
        int lane = tid & 31;

        unsigned int* xsw = (unsigned int*)u.g.xs;
        for (int r = wid; r < 64; r += 8) {
            const float* src = x + (size_t)(row0 + r) * FIN + kbeg;
            for (int k = lane; k < KCH; k += 32) {
                float v = (k < klen) ? src[k] : 0.f;
                xsw[r * KCH + k] = __float_as_uint(v);
            }
        }
        unsigned int* wsw = (unsigned int*)u.g.ws;
        for (int l = tid; l < KCH * 64; l += 256) {
            int k = l >> 6, c = l & 63;
            float v = (k < klen) ? W1[(size_t)(kbeg + k) * NH + c] : 0.f;
            wsw[(c & 7) * (KP * 16) + (k >> 1) * 16 + ((c >> 3) << 1) + (k & 1)]
                = __float_as_uint(v);
        }
        __syncthreads();

        unsigned long long acc[2][8];
        #pragma unroll
        for (int i = 0; i < 2; i++)
            #pragma unroll
            for (int j = 0; j < 8; j++) acc[i][j] = 0ull;

        for (int p = 0; p < KP; p++) {
            unsigned long long x0 = u.g.xs[(rg * 2 + 0) * KP + p];
            unsigned long long x1 = u.g.xs[(rg * 2 + 1) * KP + p];
            #pragma unroll
            for (int j = 0; j < 8; j++) {
                unsigned long long wv = u.g.ws[j * (KP * 8) + p * 8 + cg];
                asm("fma.rn.f32x2 %0, %1, %2, %0;" : "+l"(acc[0][j]) : "l"(x0), "l"(wv));
                asm("fma.rn.f32x2 %0, %1, %2, %0;" : "+l"(acc[1][j]) : "l"(x1), "l"(wv));
            }
        }

        #pragma unroll
        for (int i = 0; i < 2; i++) {
            float* dst = g_p[ks] + (size_t)(row0 + rg * 2 + i) * NH + cg * 8;
            #pragma unroll
            for (int j = 0; j < 8; j += 2) {
                unsigned l0, h0, l1, h1;
                asm("mov.b64 {%0,%1}, %2;" : "=r"(l0), "=r"(h0) : "l"(acc[i][j]));
                asm("mov.b64 {%0,%1}, %2;" : "=r"(l1), "=r"(h1) : "l"(acc[i][j + 1]));
                float2 v = make_float2(__uint_as_float(l0) + __uint_as_float(h0),
                                       __uint_as_float(l1) + __uint_as_float(h1));
                *(float2*)(dst + j) = v;
            }
        }

        // last split block of this tile reduces the 16 partials into g_g1
        __shared__ int s_last;
        __threadfence();
        __syncthreads();
        if (tid == 0) {
            int old = atomicAdd(&g_tick[tile], 1);
            s_last = (old == KSPLIT - 1);
        }
        __syncthreads();
        if (s_last) {
            for (int l = tid; l < 64 * 16; l += 256) {
                float4 s = make_float4(0.f, 0.f, 0.f, 0.f);
                #pragma unroll
                for (int q = 0; q < KSPLIT; q++) {
                    float4 v = *(const float4*)(g_p[q] + (size_t)row0 * NH + l * 4);
                    s.x += v.x; s.y += v.y; s.z += v.z; s.w += v.w;
                }
                *(float4*)(g_g1 + (size_t)row0 * NH + l * 4) = s;
            }
            if (tid == 0) g_tick[tile] = 0;   // reset for next replay
        }
    } else {
        // ---- CSR build (8 rows/block, warp per row) + flag reset ----
        int cb   = blockIdx.x - TILES * KSPLIT;
        int row  = cb * 8 + (tid >> 5);
        int lane = tid & 31;
        // dtype probe: bytes i*(NN+1), i=1..3 are diagonal self-loops for u8
        // (nonzero) but land on bytes 1..3 of 4-byte widened bool (zero).
        bool isu8 = adjb[1 * (NN + 1)] && adjb[2 * (NN + 1)] && adjb[3 * (NN + 1)];
        unsigned m[48];
        if (isu8) {
            const unsigned char* rp = adjb + (size_t)row * NN;
            #pragma unroll
            for (int q = 0; q < 48; q++)
                m[q] = __ballot_sync(0xffffffffu, rp[q * 32 + lane] != 0);
        } else {
            const unsigned int* rp = (const unsigned int*)adjb + (size_t)row * NN;
            #pragma unroll
            for (int q = 0; q < 48; q++)
                m[q] = __ballot_sync(0xffffffffu, rp[q * 32 + lane] != 0u);
        }
        int base = 0;
        #pragma unroll
        for (int q = 0; q < 48; q++) {
            unsigned b = m[q];
            if (b & (1u << lane)) {
                int pos = base + __popc(b & ((1u << lane) - 1u));
                if (pos < MAXDEG) g_nbr[row * MAXDEG + pos] = q * 32 + lane;
            }
            base += __popc(b);
        }
        if (lane == 0) {
            g_cnt[row]  = base < MAXDEG ? base : MAXDEG;
            g_flag[row] = 0;               // reset for this replay (pre-barrier)
        }
    }

    // ======================= GLOBAL BARRIER =======================
    // All 576 blocks are co-resident (45KB smem, <=64 regs -> 4 blocks/SM).
    // Monotonic ticket: no reset needed across graph replays.
    __threadfence();
    __syncthreads();
    if (tid == 0) {
        int tk = atomicAdd(&g_done, 1);
        s_target = (tk / NBLK) * NBLK + NBLK;
    }
    __syncthreads();
    if (tid == 0) {
        while (*(volatile int*)&g_done < s_target) { }
    }
    __syncthreads();
    __threadfence();

    // ======================= PHASE B =======================
    if (blockIdx.x >= 384) return;   // CSR blocks done

    int slot = tid >> 6;             // 0..3 node slots
    int t    = tid & 63;
    int i    = blockIdx.x * 4 + slot;
    int cnt  = g_cnt[i];
    int jl   = t >> 3;
    int h    = t & 7;

    if (tid < HF) u.a.a1s[tid] = a1v[tid];
    if (tid >= 64 && tid < 64 + NC) u.a.a2s[tid - 64] = a2v[tid - 64];
    for (int l = tid; l < NH * NC; l += 256) u.a.w2s[l] = W2[l];
    if (t < cnt) u.a.nb[slot][t] = g_nbr[i * MAXDEG + t];
    u.a.gis[slot][t] = g_g1[(size_t)i * NH + t];
    __syncthreads();

    // scores e[j][h] = sum_f a1[f]*lrelu(gi[h,f] + g1[nb[j]][h,f]) (from L2)
    for (int j = jl; j < cnt; j += 8) {
        const float* gr = g_g1 + (size_t)u.a.nb[slot][j] * NH + h * 8;
        float e = 0.f;
        #pragma unroll
        for (int f = 0; f < 8; f++) {
            float s = u.a.gis[slot][h * 8 + f] + gr[f];
            s = (s > 0.f) ? s : NEG_SLOPE * s;
            e += u.a.a1s[f] * s;
        }
        u.a.es[slot][j][h] = e;
    }
    __syncthreads();

    // parallel softmax (8-way partials per head)
    {
        float lm = -INFINITY;
        for (int j = jl; j < cnt; j += 8) lm = fmaxf(lm, u.a.es[slot][j][h]);
        u.a.pm[slot][h][jl] = lm;
    }
    __syncthreads();
    if (t < HEADS) {
        float m = u.a.pm[slot][t][0];
        #pragma unroll
        for (int q = 1; q < 8; q++) m = fmaxf(m, u.a.pm[slot][t][q]);
        u.a.mh[slot][t] = m;
    }
    __syncthreads();
    {
        float m = u.a.mh[slot][h];
        float ls = 0.f;
        for (int j = jl; j < cnt; j += 8) {
            float w = __expf(u.a.es[slot][j][h] - m);
            u.a.es[slot][j][h] = w;
            ls += w;
        }
        u.a.pm[slot][h][jl] = ls;
    }
    __syncthreads();
    if (t < HEADS) {
        float s = 0.f;
        #pragma unroll
        for (int q = 0; q < 8; q++) s += u.a.pm[slot][t][q];
        u.a.ssum[slot][t] = s;
    }
    __syncthreads();

    // aggregate (rows from L2) + ELU
    {
        int hh = t >> 3;
        float acc = 0.f;
        #pragma unroll 4
        for (int j = 0; j < cnt; j++)
            acc += u.a.es[slot][j][hh] * g_g1[(size_t)u.a.nb[slot][j] * NH + t];
        acc /= u.a.ssum[slot][hh];
        u.a.h1s[slot][t] = (acc > 0.f) ? acc : (__expf(acc) - 1.f);
    }
    __syncthreads();

    // fused GEMM2 -> publish g_g2 row + ready flag
    if (t < NC) {
        float acc = 0.f;
        #pragma unroll
        for (int k = 0; k < NH; k++) acc += u.a.h1s[slot][k] * u.a.w2s[k * NC + t];
        g_g2[(size_t)i * NC + t] = acc;
        __threadfence();
    }
    __syncthreads();
    if (t == 0) atomicExch(&g_flag[i], 1);

    // ---- phase B2: wait for neighbor rows, attention layer 2 ----
    if (t < 32) {
        for (int jj = t; jj < cnt; jj += 32)
            while (((volatile int*)g_flag)[u.a.nb[slot][jj]] == 0) { }
    }
    __syncthreads();
    __threadfence();

    if (t < 32) {
        int lane = t;
        float a2r[NC], g2i[NC];
        #pragma unroll
        for (int c = 0; c < NC; c++) {
            a2r[c] = u.a.a2s[c];
            g2i[c] = g_g2[(size_t)i * NC + c];
        }
        const int QMAX = (MAXDEG + 31) / 32;   // 2
        int   njv[QMAX];
        float ev[QMAX];
        int nq = 0;
        float m = -INFINITY;
        for (int jj = lane; jj < cnt; jj += 32) {
            int nj = u.a.nb[slot][jj];
            njv[nq] = nj;
            float e = 0.f;
            #pragma unroll
            for (int c = 0; c < NC; c++) {
                float s = g2i[c] + g_g2[(size_t)nj * NC + c];
                s = (s > 0.f) ? s : NEG_SLOPE * s;
                e += a2r[c] * s;
            }
            ev[nq++] = e;
            m = fmaxf(m, e);
        }
        #pragma unroll
        for (int o = 16; o > 0; o >>= 1) m = fmaxf(m, __shfl_xor_sync(0xffffffffu, m, o));

        float sum = 0.f;
        float acc[NC];
        #pragma unroll
        for (int c = 0; c < NC; c++) acc[c] = 0.f;
        for (int q = 0; q < nq; q++) {
            float w = __expf(ev[q] - m);
            sum += w;
            #pragma unroll
            for (int c = 0; c < NC; c++) acc[c] += w * g_g2[(size_t)njv[q] * NC + c];
        }
        #pragma unroll
        for (int o = 16; o > 0; o >>= 1) sum += __shfl_xor_sync(0xffffffffu, sum, o);
        float inv = 1.f / sum;

        #pragma unroll
        for (int c = 0; c < NC; c++) {
            float v = acc[c];
            #pragma unroll
            for (int o = 16; o > 0; o >>= 1) v += __shfl_xor_sync(0xffffffffu, v, o);
            if (lane == 0) out[(size_t)i * NC + c] = v * inv;
        }
    }
}

// ---------------------------------------------------------------------------
extern "C" void kernel_launch(void* const* d_in, const int* in_sizes, int n_in,
                              void* d_out, int out_size) {
    const float*         x   = (const float*)d_in[0];
    const unsigned char* adj = (const unsigned char*)d_in[1];
    const float*         W1  = (const float*)d_in[2];
    const float*         a1  = (const float*)d_in[3];
    const float*         W2  = (const float*)d_in[4];
    const float*         a2  = (const float*)d_in[5];
    float*               out = (float*)d_out;

    k_all<<<NBLK, 256>>>(x, W1, adj, a1, W2, a2, out);
}